// round 17
// baseline (speedup 1.0000x reference)
#include <cuda_runtime.h>

// Reference semantics: image (B,M,N,2) raw-reinterpreted as (2B,M,N) planes;
// flow2[p] = flow[p>>1]; out[p*MN + y*N + x] = bilinear(plane p, x+dx, y+dy),
// zero outside bounds. Row-aligned mapping: block = 2 rows of one batch,
// blockDim = 384 (x = threadIdx.x), no per-pixel div/mod.
// ROWS=2 keeps the full 16-gather batch spill-free at 34 regs;
// __launch_bounds__(384,5) -> 5 blocks/SM = 1920 thr = 93.8% occupancy.

#define MM 384
#define NN 384
#define MN (MM * NN)
#define ROWS 2

__global__ __launch_bounds__(384, 5) void warp_kernel(
    const float*  __restrict__ image,  // 2B*MN floats (raw)
    const float2* __restrict__ flow,   // B*MN float2
    float*        __restrict__ out)    // 2B*MN floats (raw)
{
    int bid = blockIdx.x;
    int b   = bid / 192;             // uniform per block
    int y0  = (bid - b * 192) * ROWS;
    int x   = threadIdx.x;

    const size_t pbase = (size_t)(2 * b) * MN;        // plane-A base
    const float2* frow = flow + (size_t)b * MN + y0 * NN + x;

    float2 f[ROWS];
#pragma unroll
    for (int i = 0; i < ROWS; i++)
        f[i] = __ldcs(frow + i * NN);

    int   o00[ROWS], o01[ROWS], o10[ROWS], o11[ROWS];
    float w00[ROWS], w01[ROWS], w10[ROWS], w11[ROWS];

#pragma unroll
    for (int i = 0; i < ROWS; i++) {
        float xs = (float)x + f[i].x;
        float ys = (float)(y0 + i) + f[i].y;

        float x0f = floorf(xs);
        float y0f = floorf(ys);
        float wx = xs - x0f;
        float wy = ys - y0f;
        int xi0 = (int)x0f;
        int yi0 = (int)y0f;
        int xi1 = xi0 + 1;
        int yi1 = yi0 + 1;

        float wxm0 = ((unsigned)xi0 < (unsigned)NN) ? (1.0f - wx) : 0.0f;
        float wxm1 = ((unsigned)xi1 < (unsigned)NN) ? wx : 0.0f;
        float wym0 = ((unsigned)yi0 < (unsigned)MM) ? (1.0f - wy) : 0.0f;
        float wym1 = ((unsigned)yi1 < (unsigned)MM) ? wy : 0.0f;

        int xc0 = min(max(xi0, 0), NN - 1);
        int xc1 = min(max(xi1, 0), NN - 1);
        int yc0 = min(max(yi0, 0), MM - 1);
        int yc1 = min(max(yi1, 0), MM - 1);

        o00[i] = yc0 * NN + xc0;
        o01[i] = yc0 * NN + xc1;
        o10[i] = yc1 * NN + xc0;
        o11[i] = yc1 * NN + xc1;
        w00[i] = wym0 * wxm0;
        w01[i] = wym0 * wxm1;
        w10[i] = wym1 * wxm0;
        w11[i] = wym1 * wxm1;
    }

    const float* pA = image + pbase;
    const float* pB = pA + MN;

    // full 16-gather batch, spill-free at this register budget
    float vA00[ROWS], vA01[ROWS], vA10[ROWS], vA11[ROWS];
    float vB00[ROWS], vB01[ROWS], vB10[ROWS], vB11[ROWS];
#pragma unroll
    for (int i = 0; i < ROWS; i++) {
        vA00[i] = __ldg(pA + o00[i]);
        vA01[i] = __ldg(pA + o01[i]);
        vA10[i] = __ldg(pA + o10[i]);
        vA11[i] = __ldg(pA + o11[i]);
        vB00[i] = __ldg(pB + o00[i]);
        vB01[i] = __ldg(pB + o01[i]);
        vB10[i] = __ldg(pB + o10[i]);
        vB11[i] = __ldg(pB + o11[i]);
    }

    float* oA = out + pbase + y0 * NN + x;
    float* oB = oA + MN;
#pragma unroll
    for (int i = 0; i < ROWS; i++) {
        float accA = vA00[i] * w00[i] + vA01[i] * w01[i]
                   + vA10[i] * w10[i] + vA11[i] * w11[i];
        float accB = vB00[i] * w00[i] + vB01[i] * w01[i]
                   + vB10[i] * w10[i] + vB11[i] * w11[i];
        __stcs(oA + i * NN, accA);
        __stcs(oB + i * NN, accB);
    }
}

extern "C" void kernel_launch(void* const* d_in, const int* in_sizes, int n_in,
                              void* d_out, int out_size)
{
    const float*  image = (const float*)d_in[0];
    const float2* flow  = (const float2*)d_in[1];
    float* out = (float*)d_out;

    int B = out_size / (2 * MN);
    int blocks = B * (MM / ROWS);   // 64 * 192 = 12288
    warp_kernel<<<blocks, 384>>>(image, flow, out);
}